// round 4
// baseline (speedup 1.0000x reference)
#include <cuda_runtime.h>
#include <cstdint>

#define NN 50000
#define EE 800000
#define ET (EE + NN)        // edges + self loops = 850000
#define INF_NEG (-1e30f)

// output layout: xo_logis [N,8] | xc_logis [N,8] | xco_logis [N,8] | elu(xo) [N,256] | elu(xc) [N,256]
#define O0 0
#define O1 (NN*8)
#define O2 (2*NN*8)
#define O3 (3*NN*8)
#define O4 (3*NN*8 + NN*256)

// ------------------- static scratch (device globals; no allocs) -------------------
__device__ int   g_deg[NN];
__device__ int   g_rowptr[NN + 1];
__device__ int   g_wptr[NN];
__device__ int   g_srt[ET];

__device__ float g_hfeat[(size_t)NN * 256];   // x @ W_feat (pre-aggregation)
__device__ float g_h1[(size_t)NN * 256];      // elu(agg + b)  (== xco input)
__device__ float g_xo[(size_t)NN * 256];
__device__ float g_xc[(size_t)NN * 256];
__device__ float4 g_escr[ET];                 // per-edge e / p scratch (4 heads)

__device__ float g_als[NN * 4], g_ald[NN * 4];     // big conv alphas
__device__ float g_gobj[NN * 16], g_gctx[NN * 16], g_gco[NN * 16];
__device__ float g_also[NN * 2], g_aldo[NN * 2];
__device__ float g_alsc[NN * 2], g_aldc[NN * 2];
__device__ float g_alsx[NN * 2], g_aldx[NN * 2];

__device__ __forceinline__ float lrelu(float v) { return v > 0.f ? v : 0.2f * v; }
__device__ __forceinline__ float eluf(float v)  { return v > 0.f ? v : expm1f(v); }

// ------------------- CSR build -------------------
__global__ void k_zero_deg() {
    int i = blockIdx.x * blockDim.x + threadIdx.x;
    if (i < NN) g_deg[i] = 0;
}

__global__ void k_hist(const int* __restrict__ ei) {
    int i = blockIdx.x * blockDim.x + threadIdx.x;
    if (i >= ET) return;
    int d = (i < EE) ? ei[EE + i] : (i - EE);
    atomicAdd(&g_deg[d], 1);
}

__global__ void k_scan() {
    __shared__ int sums[1024];
    int tid = threadIdx.x;
    const int chunk = (NN + 1023) / 1024;
    int start = tid * chunk;
    int s = 0;
    for (int i = 0; i < chunk; i++) {
        int idx = start + i;
        if (idx < NN) s += g_deg[idx];
    }
    sums[tid] = s;
    __syncthreads();
    for (int off = 1; off < 1024; off <<= 1) {
        int v = 0;
        if (tid >= off) v = sums[tid - off];
        __syncthreads();
        if (tid >= off) sums[tid] += v;
        __syncthreads();
    }
    int prefix = (tid == 0) ? 0 : sums[tid - 1];
    for (int i = 0; i < chunk; i++) {
        int idx = start + i;
        if (idx < NN) {
            g_rowptr[idx] = prefix;
            g_wptr[idx] = prefix;
            prefix += g_deg[idx];
        }
    }
    if (tid == 0) g_rowptr[NN] = sums[1023];
}

__global__ void k_scatter(const int* __restrict__ ei) {
    int i = blockIdx.x * blockDim.x + threadIdx.x;
    if (i >= ET) return;
    int s, d;
    if (i < EE) { s = ei[i]; d = ei[EE + i]; }
    else        { s = d = i - EE; }
    int pos = atomicAdd(&g_wptr[d], 1);
    g_srt[pos] = s;
}

// ------------------- GEMM1: hfeat = x @ W_feat, plus al_src/al_dst -------------------
// block: 256 threads; 8 node rows per block (50000 % 8 == 0)
__global__ void k_gemm1(const float* __restrict__ x, const float* __restrict__ Wf,
                        const float* __restrict__ a_s, const float* __restrict__ a_d) {
    __shared__ float xs[8][128];
    __shared__ float part_s[8][8], part_d[8][8];
    int tid = threadIdx.x;
    int n0 = blockIdx.x * 8;

    for (int i = tid; i < 8 * 128; i += 256) {
        int r = i >> 7, k = i & 127;
        xs[r][k] = x[(size_t)(n0 + r) * 128 + k];
    }
    __syncthreads();

    float acc[8] = {0, 0, 0, 0, 0, 0, 0, 0};
    for (int k = 0; k < 128; k++) {
        float w = Wf[k * 256 + tid];
#pragma unroll
        for (int r = 0; r < 8; r++) acc[r] += xs[r][k] * w;
    }

    float asv = a_s[tid];   // a_src_feat flat [h*64+c] == tid
    float adv = a_d[tid];
    int warp = tid >> 5, lane = tid & 31;
#pragma unroll
    for (int r = 0; r < 8; r++) {
        g_hfeat[(size_t)(n0 + r) * 256 + tid] = acc[r];
        float ps = acc[r] * asv, pd = acc[r] * adv;
        for (int o = 16; o; o >>= 1) {
            ps += __shfl_xor_sync(~0u, ps, o);
            pd += __shfl_xor_sync(~0u, pd, o);
        }
        if (lane == 0) { part_s[r][warp] = ps; part_d[r][warp] = pd; }
    }
    __syncthreads();
    if (tid < 32) {
        int r = tid >> 2, h = tid & 3;
        g_als[(n0 + r) * 4 + h] = part_s[r][2 * h] + part_s[r][2 * h + 1];
        g_ald[(n0 + r) * 4 + h] = part_d[r][2 * h] + part_d[r][2 * h + 1];
    }
}

// ------------------- big conv: warp per dst node -------------------
__global__ void k_conv1(const float* __restrict__ b_feat, const float* __restrict__ W_mlp,
                        const float* __restrict__ b_mlp, float* __restrict__ out) {
    int gwarp = (blockIdx.x * blockDim.x + threadIdx.x) >> 5;
    int lane = threadIdx.x & 31;
    if (gwarp >= NN) return;
    int n = gwarp;
    int beg = g_rowptr[n], end = g_rowptr[n + 1];

    const float4* als4 = (const float4*)g_als;
    float4 ad = ((const float4*)g_ald)[n];

    // pass 1: e = lrelu(als[src] + ald[dst]); store; track max
    float4 mx = make_float4(INF_NEG, INF_NEG, INF_NEG, INF_NEG);
    for (int i = beg + lane; i < end; i += 32) {
        int s = g_srt[i];
        float4 as = als4[s];
        float4 e;
        e.x = lrelu(as.x + ad.x);
        e.y = lrelu(as.y + ad.y);
        e.z = lrelu(as.z + ad.z);
        e.w = lrelu(as.w + ad.w);
        g_escr[i] = e;
        mx.x = fmaxf(mx.x, e.x); mx.y = fmaxf(mx.y, e.y);
        mx.z = fmaxf(mx.z, e.z); mx.w = fmaxf(mx.w, e.w);
    }
    for (int o = 16; o; o >>= 1) {
        mx.x = fmaxf(mx.x, __shfl_xor_sync(~0u, mx.x, o));
        mx.y = fmaxf(mx.y, __shfl_xor_sync(~0u, mx.y, o));
        mx.z = fmaxf(mx.z, __shfl_xor_sync(~0u, mx.z, o));
        mx.w = fmaxf(mx.w, __shfl_xor_sync(~0u, mx.w, o));
    }

    // pass 2: p = exp(e - m); overwrite scratch; sum
    float4 sm = make_float4(0, 0, 0, 0);
    for (int i = beg + lane; i < end; i += 32) {
        float4 e = g_escr[i];
        float4 p;
        p.x = __expf(e.x - mx.x); p.y = __expf(e.y - mx.y);
        p.z = __expf(e.z - mx.z); p.w = __expf(e.w - mx.w);
        g_escr[i] = p;
        sm.x += p.x; sm.y += p.y; sm.z += p.z; sm.w += p.w;
    }
    for (int o = 16; o; o >>= 1) {
        sm.x += __shfl_xor_sync(~0u, sm.x, o);
        sm.y += __shfl_xor_sync(~0u, sm.y, o);
        sm.z += __shfl_xor_sync(~0u, sm.z, o);
        sm.w += __shfl_xor_sync(~0u, sm.w, o);
    }
    float4 inv;
    inv.x = 1.f / (sm.x + 1e-16f); inv.y = 1.f / (sm.y + 1e-16f);
    inv.z = 1.f / (sm.z + 1e-16f); inv.w = 1.f / (sm.w + 1e-16f);

    // pass 3: accumulate 256 channels across edges (lane owns c = lane + 32k; head = k>>1)
    float acc[8] = {0, 0, 0, 0, 0, 0, 0, 0};
    for (int base = beg; base < end; base += 32) {
        int idx = base + lane;
        int sl = 0;
        float4 pl = make_float4(0, 0, 0, 0);
        if (idx < end) { sl = g_srt[idx]; pl = g_escr[idx]; }
        int cnt = min(32, end - base);
        for (int j = 0; j < cnt; j++) {
            int s = __shfl_sync(~0u, sl, j);
            float a0 = __shfl_sync(~0u, pl.x, j) * inv.x;
            float a1 = __shfl_sync(~0u, pl.y, j) * inv.y;
            float a2 = __shfl_sync(~0u, pl.z, j) * inv.z;
            float a3 = __shfl_sync(~0u, pl.w, j) * inv.w;
            const float* hr = g_hfeat + (size_t)s * 256;
            acc[0] += a0 * hr[lane];        acc[1] += a0 * hr[lane + 32];
            acc[2] += a1 * hr[lane + 64];   acc[3] += a1 * hr[lane + 96];
            acc[4] += a2 * hr[lane + 128];  acc[5] += a2 * hr[lane + 160];
            acc[6] += a3 * hr[lane + 192];  acc[7] += a3 * hr[lane + 224];
        }
    }

    // epilogue: h1 = elu(acc + b); node-attention softmax; xo/xc; elu outputs
    float l0 = 0.f, l1 = 0.f;
    float he[8];
#pragma unroll
    for (int k = 0; k < 8; k++) {
        int c = lane + 32 * k;
        float v = acc[k] + b_feat[c];
        float h = eluf(v);
        he[k] = h;
        g_h1[(size_t)n * 256 + c] = h;
        l0 += h * W_mlp[2 * c];
        l1 += h * W_mlp[2 * c + 1];
    }
    for (int o = 16; o; o >>= 1) {
        l0 += __shfl_xor_sync(~0u, l0, o);
        l1 += __shfl_xor_sync(~0u, l1, o);
    }
    l0 += b_mlp[0];
    l1 += b_mlp[1];
    float mm = fmaxf(l0, l1);
    float e0 = __expf(l0 - mm), e1 = __expf(l1 - mm);
    float inv2 = 1.f / (e0 + e1);
    float att0 = e0 * inv2, att1 = e1 * inv2;
#pragma unroll
    for (int k = 0; k < 8; k++) {
        int c = lane + 32 * k;
        float xov = att0 * he[k];
        float xcv = att1 * he[k];
        g_xo[(size_t)n * 256 + c] = xov;
        g_xc[(size_t)n * 256 + c] = xcv;
        out[O3 + (size_t)n * 256 + c] = eluf(xov);
        out[O4 + (size_t)n * 256 + c] = eluf(xcv);
    }
}

// ------------------- GEMM2: 3 small projections + al dots, block per node -------------------
__global__ void k_gemm2(const float* __restrict__ Wo, const float* __restrict__ Wc,
                        const float* __restrict__ Wx,
                        const float* __restrict__ aso, const float* __restrict__ ado,
                        const float* __restrict__ asc, const float* __restrict__ adc,
                        const float* __restrict__ asx, const float* __restrict__ adx) {
    int n = blockIdx.x;
    int t = threadIdx.x;   // 64 threads
    __shared__ float sxo[256], sxc[256], sh[256];
    __shared__ float gsh[48];

    ((float4*)sxo)[t] = ((const float4*)(g_xo + (size_t)n * 256))[t];
    ((float4*)sxc)[t] = ((const float4*)(g_xc + (size_t)n * 256))[t];
    ((float4*)sh)[t]  = ((const float4*)(g_h1 + (size_t)n * 256))[t];
    __syncthreads();

    if (t < 48) {
        const float* src;
        const float* W;
        int c = t & 15;
        if (t < 16)      { src = sxo; W = Wo; }
        else if (t < 32) { src = sxc; W = Wc; }
        else             { src = sh;  W = Wx; }
        float acc = 0.f;
        for (int k = 0; k < 256; k++) acc += src[k] * W[k * 16 + c];
        gsh[t] = acc;
        if (t < 16)      g_gobj[n * 16 + c] = acc;
        else if (t < 32) g_gctx[n * 16 + c] = acc;
        else             g_gco[n * 16 + c] = acc;
    }
    __syncthreads();
    if (t < 12) {
        int conv = t >> 2, h = (t >> 1) & 1, sd = t & 1;
        const float* a = (sd == 0) ? (conv == 0 ? aso : conv == 1 ? asc : asx)
                                   : (conv == 0 ? ado : conv == 1 ? adc : adx);
        const float* g = gsh + conv * 16 + h * 8;
        float s = 0.f;
        for (int o = 0; o < 8; o++) s += g[o] * a[h * 8 + o];
        float* dstarr = (sd == 0) ? (conv == 0 ? g_also : conv == 1 ? g_alsc : g_alsx)
                                  : (conv == 0 ? g_aldo : conv == 1 ? g_aldc : g_aldx);
        dstarr[n * 2 + h] = s;
    }
}

// ------------------- small conv: warp per dst node, heads=2, C=8, mean+log_softmax -------------------
// which: 0=obj, 1=ctx, 2=co   (device-global pointers resolved INSIDE device code)
__global__ void k_conv2(int which, const float* __restrict__ b, float* __restrict__ out) {
    int gwarp = (blockIdx.x * blockDim.x + threadIdx.x) >> 5;
    int lane = threadIdx.x & 31;
    if (gwarp >= NN) return;
    int n = gwarp;

    const float* g   = (which == 0) ? g_gobj : (which == 1) ? g_gctx : g_gco;
    const float* als = (which == 0) ? g_also : (which == 1) ? g_alsc : g_alsx;
    const float* ald = (which == 0) ? g_aldo : (which == 1) ? g_aldc : g_aldx;

    int beg = g_rowptr[n], end = g_rowptr[n + 1];

    float ad0 = ald[n * 2], ad1 = ald[n * 2 + 1];

    float m0 = INF_NEG, m1 = INF_NEG;
    for (int i = beg + lane; i < end; i += 32) {
        int s = g_srt[i];
        float e0 = lrelu(als[s * 2] + ad0);
        float e1 = lrelu(als[s * 2 + 1] + ad1);
        m0 = fmaxf(m0, e0);
        m1 = fmaxf(m1, e1);
    }
    for (int o = 16; o; o >>= 1) {
        m0 = fmaxf(m0, __shfl_xor_sync(~0u, m0, o));
        m1 = fmaxf(m1, __shfl_xor_sync(~0u, m1, o));
    }

    float s0 = 0.f, s1 = 0.f;
    for (int i = beg + lane; i < end; i += 32) {
        int s = g_srt[i];
        s0 += __expf(lrelu(als[s * 2] + ad0) - m0);
        s1 += __expf(lrelu(als[s * 2 + 1] + ad1) - m1);
    }
    for (int o = 16; o; o >>= 1) {
        s0 += __shfl_xor_sync(~0u, s0, o);
        s1 += __shfl_xor_sync(~0u, s1, o);
    }
    float inv0 = 1.f / (s0 + 1e-16f), inv1 = 1.f / (s1 + 1e-16f);

    // pass 3: half-warps process alternate edges; sub-lane owns channel (head*8 + o)
    int sub = lane & 15, half = lane >> 4;
    int head = sub >> 3;
    float mh = head ? m1 : m0;
    float invh = head ? inv1 : inv0;
    float adh = head ? ad1 : ad0;
    float acc = 0.f;
    for (int i = beg + half; i < end; i += 2) {
        int s = g_srt[i];
        float e = lrelu(als[s * 2 + head] + adh);
        float alpha = __expf(e - mh) * invh;
        acc += alpha * g[s * 16 + sub];
    }
    acc += __shfl_xor_sync(~0u, acc, 16);

    // head mean + bias + log_softmax over 8 channels (lanes 0..7 valid)
    float other = __shfl_sync(~0u, acc, (lane & 15) + 8 + (lane & 16));
    float val = (acc + other) * 0.5f + b[lane & 7];
    float mv = val;
    for (int o = 4; o; o >>= 1) mv = fmaxf(mv, __shfl_xor_sync(~0u, mv, o, 8));
    float se = __expf(val - mv);
    for (int o = 4; o; o >>= 1) se += __shfl_xor_sync(~0u, se, o, 8);
    if (lane < 8) out[(size_t)n * 8 + lane] = val - mv - logf(se);
}

// ------------------- launch -------------------
extern "C" void kernel_launch(void* const* d_in, const int* in_sizes, int n_in,
                              void* d_out, int out_size) {
    const float* x      = (const float*)d_in[0];
    const int*   ei     = (const int*)d_in[1];     // int32! (JAX x64 disabled)
    const float* W_feat = (const float*)d_in[2];
    const float* a_s_f  = (const float*)d_in[3];
    const float* a_d_f  = (const float*)d_in[4];
    const float* b_feat = (const float*)d_in[5];
    const float* W_mlp  = (const float*)d_in[6];
    const float* b_mlp  = (const float*)d_in[7];
    const float* b_obj  = (const float*)d_in[11];
    const float* W_obj  = (const float*)d_in[8];
    const float* a_s_o  = (const float*)d_in[9];
    const float* a_d_o  = (const float*)d_in[10];
    const float* W_ctx  = (const float*)d_in[12];
    const float* a_s_c  = (const float*)d_in[13];
    const float* a_d_c  = (const float*)d_in[14];
    const float* b_ctx  = (const float*)d_in[15];
    const float* W_co   = (const float*)d_in[16];
    const float* a_s_x  = (const float*)d_in[17];
    const float* a_d_x  = (const float*)d_in[18];
    const float* b_co   = (const float*)d_in[19];
    float* out = (float*)d_out;

    // CSR build
    k_zero_deg<<<(NN + 255) / 256, 256>>>();
    k_hist<<<(ET + 255) / 256, 256>>>(ei);
    k_scan<<<1, 1024>>>();
    k_scatter<<<(ET + 255) / 256, 256>>>(ei);

    // big GAT conv
    k_gemm1<<<NN / 8, 256>>>(x, W_feat, a_s_f, a_d_f);
    k_conv1<<<(NN + 3) / 4, 128>>>(b_feat, W_mlp, b_mlp, out);

    // small projections + al dots
    k_gemm2<<<NN, 64>>>(W_obj, W_ctx, W_co, a_s_o, a_d_o, a_s_c, a_d_c, a_s_x, a_d_x);

    // three small GAT convs -> log_softmax outputs
    k_conv2<<<(NN + 3) / 4, 128>>>(0, b_obj, out + O0);
    k_conv2<<<(NN + 3) / 4, 128>>>(1, b_ctx, out + O1);
    k_conv2<<<(NN + 3) / 4, 128>>>(2, b_co,  out + O2);
}

// round 5
// speedup vs baseline: 1.1696x; 1.1696x over previous
#include <cuda_runtime.h>
#include <cstdint>

#define NN 50000
#define EE 800000
#define ET (EE + NN)
#define INF_NEG (-1e30f)

// output layout: xo_logis [N,8] | xc_logis [N,8] | xco_logis [N,8] | elu(xo) [N,256] | elu(xc) [N,256]
#define O0 0
#define O1 (NN*8)
#define O2 (2*NN*8)
#define O3 (3*NN*8)
#define O4 (3*NN*8 + NN*256)

// ------------------- static scratch -------------------
__device__ int   g_deg[NN];
__device__ int   g_rowptr[NN + 1];
__device__ int   g_wptr[NN];
__device__ int   g_srt[ET];

__device__ float  g_hfeat[(size_t)NN * 256];  // x @ W_feat
__device__ float  g_h1[(size_t)NN * 256];     // elu(agg + b)  (== xco conv input)
__device__ float2 g_att[NN];                  // node-attention (att0, att1)

__device__ float g_als[NN * 4], g_ald[NN * 4];   // big conv logits
__device__ float g_gall[(size_t)NN * 48];        // [obj 16 | ctx 16 | co 16] per node
__device__ float g_alsP[NN * 8], g_aldP[NN * 8]; // packed small-conv logits [c0h0,c0h1,c1h0,c1h1,c2h0,c2h1,pad,pad]

__device__ __forceinline__ float lrelu(float v) { return v > 0.f ? v : 0.2f * v; }
__device__ __forceinline__ float eluf(float v)  { return v > 0.f ? v : expm1f(v); }

// ------------------- CSR build -------------------
__global__ void k_zero_deg() {
    int i = blockIdx.x * blockDim.x + threadIdx.x;
    if (i < NN) g_deg[i] = 0;
}

__global__ void k_hist(const int* __restrict__ ei) {
    int i = blockIdx.x * blockDim.x + threadIdx.x;
    if (i >= ET) return;
    int d = (i < EE) ? ei[EE + i] : (i - EE);
    atomicAdd(&g_deg[d], 1);
}

__global__ void k_scan() {
    __shared__ int sums[1024];
    int tid = threadIdx.x;
    const int chunk = (NN + 1023) / 1024;
    int start = tid * chunk;
    int s = 0;
    for (int i = 0; i < chunk; i++) {
        int idx = start + i;
        if (idx < NN) s += g_deg[idx];
    }
    sums[tid] = s;
    __syncthreads();
    for (int off = 1; off < 1024; off <<= 1) {
        int v = 0;
        if (tid >= off) v = sums[tid - off];
        __syncthreads();
        if (tid >= off) sums[tid] += v;
        __syncthreads();
    }
    int prefix = (tid == 0) ? 0 : sums[tid - 1];
    for (int i = 0; i < chunk; i++) {
        int idx = start + i;
        if (idx < NN) {
            g_rowptr[idx] = prefix;
            g_wptr[idx] = prefix;
            prefix += g_deg[idx];
        }
    }
    if (tid == 0) g_rowptr[NN] = sums[1023];
}

__global__ void k_scatter(const int* __restrict__ ei) {
    int i = blockIdx.x * blockDim.x + threadIdx.x;
    if (i >= ET) return;
    int s, d;
    if (i < EE) { s = ei[i]; d = ei[EE + i]; }
    else        { s = d = i - EE; }
    int pos = atomicAdd(&g_wptr[d], 1);
    g_srt[pos] = s;
}

// ------------------- GEMM1: tiled 64x256, thread = 8x8 -------------------
__global__ __launch_bounds__(256) void k_gemm1(
    const float* __restrict__ x, const float* __restrict__ Wf,
    const float* __restrict__ a_s, const float* __restrict__ a_d) {
    __shared__ float xs[64][132];   // padded: bank-conflict-free column reads
    __shared__ float Bs[8][256];
    int tid = threadIdx.x;
    int n0 = blockIdx.x * 64;
    int ty = tid >> 5, tx = tid & 31;

    // load full A tile (64 rows x 128 k), coalesced float4
#pragma unroll
    for (int i = 0; i < 8; i++) {
        int idx4 = tid + i * 256;
        int row = idx4 >> 5, kq = idx4 & 31;
        float4 v = make_float4(0, 0, 0, 0);
        if (n0 + row < NN) v = *(const float4*)(x + (size_t)(n0 + row) * 128 + kq * 4);
        *(float4*)&xs[row][kq * 4] = v;
    }

    float asr[8], adr[8];
    *(float4*)&asr[0] = *(const float4*)(a_s + tx * 8);
    *(float4*)&asr[4] = *(const float4*)(a_s + tx * 8 + 4);
    *(float4*)&adr[0] = *(const float4*)(a_d + tx * 8);
    *(float4*)&adr[4] = *(const float4*)(a_d + tx * 8 + 4);

    float acc[8][8];
#pragma unroll
    for (int i = 0; i < 8; i++)
#pragma unroll
        for (int j = 0; j < 8; j++) acc[i][j] = 0.f;

    for (int kt = 0; kt < 16; kt++) {
        __syncthreads();
#pragma unroll
        for (int i = 0; i < 2; i++) {
            int idx4 = tid + i * 256;
            int kk = idx4 >> 6, col4 = (idx4 & 63) * 4;
            *(float4*)&Bs[kk][col4] = *(const float4*)(Wf + (size_t)(kt * 8 + kk) * 256 + col4);
        }
        __syncthreads();
#pragma unroll
        for (int kk = 0; kk < 8; kk++) {
            float a_frag[8], b_frag[8];
#pragma unroll
            for (int i = 0; i < 8; i++) a_frag[i] = xs[ty * 8 + i][kt * 8 + kk];
            *(float4*)&b_frag[0] = *(float4*)&Bs[kk][tx * 8];
            *(float4*)&b_frag[4] = *(float4*)&Bs[kk][tx * 8 + 4];
#pragma unroll
            for (int i = 0; i < 8; i++)
#pragma unroll
                for (int j = 0; j < 8; j++) acc[i][j] += a_frag[i] * b_frag[j];
        }
    }

    // epilogue: store hfeat rows + fused attention-logit dots
#pragma unroll
    for (int i = 0; i < 8; i++) {
        int row = n0 + ty * 8 + i;
        bool ok = row < NN;
        if (ok) {
            *(float4*)(g_hfeat + (size_t)row * 256 + tx * 8)     = *(float4*)&acc[i][0];
            *(float4*)(g_hfeat + (size_t)row * 256 + tx * 8 + 4) = *(float4*)&acc[i][4];
        }
        float ps = 0.f, pd = 0.f;
#pragma unroll
        for (int j = 0; j < 8; j++) { ps += acc[i][j] * asr[j]; pd += acc[i][j] * adr[j]; }
        for (int o = 1; o < 8; o <<= 1) {
            ps += __shfl_xor_sync(~0u, ps, o);
            pd += __shfl_xor_sync(~0u, pd, o);
        }
        if ((tx & 7) == 0 && ok) {
            int h = tx >> 3;
            g_als[row * 4 + h] = ps;
            g_ald[row * 4 + h] = pd;
        }
    }
}

// ------------------- big conv: warp per dst node, 2-pass online softmax -------------------
__global__ void k_conv1(const float* __restrict__ b_feat, const float* __restrict__ W_mlp,
                        const float* __restrict__ b_mlp, float* __restrict__ out) {
    int gwarp = (blockIdx.x * blockDim.x + threadIdx.x) >> 5;
    int lane = threadIdx.x & 31;
    if (gwarp >= NN) return;
    int n = gwarp;
    int beg = g_rowptr[n], end = g_rowptr[n + 1];

    const float4* als4 = (const float4*)g_als;
    float4 ad = ((const float4*)g_ald)[n];

    // pass 1: online (max, sum) per head
    float m[4] = {INF_NEG, INF_NEG, INF_NEG, INF_NEG};
    float s[4] = {0, 0, 0, 0};
    for (int i = beg + lane; i < end; i += 32) {
        int sv = g_srt[i];
        float4 as = als4[sv];
        float e[4];
        e[0] = lrelu(as.x + ad.x); e[1] = lrelu(as.y + ad.y);
        e[2] = lrelu(as.z + ad.z); e[3] = lrelu(as.w + ad.w);
#pragma unroll
        for (int k = 0; k < 4; k++) {
            float nm = fmaxf(m[k], e[k]);
            s[k] = s[k] * __expf(m[k] - nm) + __expf(e[k] - nm);
            m[k] = nm;
        }
    }
    for (int o = 16; o; o >>= 1) {
#pragma unroll
        for (int k = 0; k < 4; k++) {
            float om = __shfl_xor_sync(~0u, m[k], o);
            float os = __shfl_xor_sync(~0u, s[k], o);
            float nm = fmaxf(m[k], om);
            s[k] = s[k] * __expf(m[k] - nm) + os * __expf(om - nm);
            m[k] = nm;
        }
    }
    float inv[4];
#pragma unroll
    for (int k = 0; k < 4; k++) inv[k] = 1.f / (s[k] + 1e-16f);

    // pass 2: gather-accumulate 256 channels
    float acc[8] = {0, 0, 0, 0, 0, 0, 0, 0};
    for (int base = beg; base < end; base += 32) {
        int idx = base + lane;
        int sl = 0;
        float p[4] = {0, 0, 0, 0};
        if (idx < end) {
            sl = g_srt[idx];
            float4 as = als4[sl];
            p[0] = __expf(lrelu(as.x + ad.x) - m[0]) * inv[0];
            p[1] = __expf(lrelu(as.y + ad.y) - m[1]) * inv[1];
            p[2] = __expf(lrelu(as.z + ad.z) - m[2]) * inv[2];
            p[3] = __expf(lrelu(as.w + ad.w) - m[3]) * inv[3];
        }
        int cnt = min(32, end - base);
        for (int j = 0; j < cnt; j++) {
            int sb = __shfl_sync(~0u, sl, j);
            float a0 = __shfl_sync(~0u, p[0], j);
            float a1 = __shfl_sync(~0u, p[1], j);
            float a2 = __shfl_sync(~0u, p[2], j);
            float a3 = __shfl_sync(~0u, p[3], j);
            const float* hr = g_hfeat + (size_t)sb * 256;
            acc[0] += a0 * hr[lane];        acc[1] += a0 * hr[lane + 32];
            acc[2] += a1 * hr[lane + 64];   acc[3] += a1 * hr[lane + 96];
            acc[4] += a2 * hr[lane + 128];  acc[5] += a2 * hr[lane + 160];
            acc[6] += a3 * hr[lane + 192];  acc[7] += a3 * hr[lane + 224];
        }
    }

    // epilogue: h1 = elu(acc + b); node-attention softmax; elu(xo)/elu(xc) outputs
    float l0 = 0.f, l1 = 0.f;
    float he[8];
#pragma unroll
    for (int k = 0; k < 8; k++) {
        int c = lane + 32 * k;
        float h = eluf(acc[k] + b_feat[c]);
        he[k] = h;
        g_h1[(size_t)n * 256 + c] = h;
        l0 += h * W_mlp[2 * c];
        l1 += h * W_mlp[2 * c + 1];
    }
    for (int o = 16; o; o >>= 1) {
        l0 += __shfl_xor_sync(~0u, l0, o);
        l1 += __shfl_xor_sync(~0u, l1, o);
    }
    l0 += b_mlp[0];
    l1 += b_mlp[1];
    float mm = fmaxf(l0, l1);
    float e0 = __expf(l0 - mm), e1 = __expf(l1 - mm);
    float inv2 = 1.f / (e0 + e1);
    float att0 = e0 * inv2, att1 = e1 * inv2;
    if (lane == 0) g_att[n] = make_float2(att0, att1);
#pragma unroll
    for (int k = 0; k < 8; k++) {
        int c = lane + 32 * k;
        out[O3 + (size_t)n * 256 + c] = eluf(att0 * he[k]);
        out[O4 + (size_t)n * 256 + c] = eluf(att1 * he[k]);
    }
}

// ------------------- GEMM2: Y = h1 @ [Wobj|Wctx|Wco], att-scaled; + logit dots -------------------
// 16 nodes per block, 256 threads: thread = (node, channel)
__global__ __launch_bounds__(256) void k_gemm2(
    const float* __restrict__ Wo, const float* __restrict__ Wc, const float* __restrict__ Wx,
    const float* __restrict__ aso, const float* __restrict__ ado,
    const float* __restrict__ asc, const float* __restrict__ adc,
    const float* __restrict__ asx, const float* __restrict__ adx) {
    __shared__ float sh[16][260];
    __shared__ float ws[16][268];   // transposed W for current conv: ws[c][k]
    __shared__ float ysm[16][52];
    int tid = threadIdx.x;
    int n0 = blockIdx.x * 16;

#pragma unroll
    for (int i = 0; i < 4; i++) {
        int idx4 = tid + i * 256;
        int row = idx4 >> 6, kq = idx4 & 63;
        *(float4*)&sh[row][kq * 4] = *(const float4*)(g_h1 + (size_t)(n0 + row) * 256 + kq * 4);
    }

    int node = tid >> 4, c = tid & 15;
    float2 att = g_att[n0 + node];

    for (int v = 0; v < 3; v++) {
        const float* W = (v == 0) ? Wo : (v == 1) ? Wc : Wx;
        float scale = (v == 0) ? att.x : (v == 1) ? att.y : 1.f;
        __syncthreads();
#pragma unroll
        for (int i = 0; i < 16; i++) {
            int idx = tid + i * 256;
            ws[idx & 15][idx >> 4] = W[idx];
        }
        __syncthreads();
        float a = 0.f;
#pragma unroll 8
        for (int k = 0; k < 256; k += 4) {
            float4 hv = *(float4*)&sh[node][k];
            float4 wv = *(float4*)&ws[c][k];
            a += hv.x * wv.x + hv.y * wv.y + hv.z * wv.z + hv.w * wv.w;
        }
        float y = a * scale;
        g_gall[(size_t)(n0 + node) * 48 + v * 16 + c] = y;
        ysm[node][v * 16 + c] = y;
    }
    __syncthreads();
    if (tid < 192) {
        int nd = tid / 12, r = tid % 12;
        int v = r >> 2, h = (r >> 1) & 1, sd = r & 1;
        const float* a = sd ? ((v == 0) ? ado : (v == 1) ? adc : adx)
                            : ((v == 0) ? aso : (v == 1) ? asc : asx);
        float s = 0.f;
#pragma unroll
        for (int o = 0; o < 8; o++) s += ysm[nd][v * 16 + h * 8 + o] * a[h * 8 + o];
        float* dstp = sd ? g_aldP : g_alsP;
        dstp[(n0 + nd) * 8 + v * 2 + h] = s;
    }
}

// ------------------- merged small convs: warp per dst node, 2-pass -------------------
__global__ void k_conv2m(const float* __restrict__ b_obj, const float* __restrict__ b_ctx,
                         const float* __restrict__ b_co, float* __restrict__ out) {
    int gwarp = (blockIdx.x * blockDim.x + threadIdx.x) >> 5;
    int lane = threadIdx.x & 31;
    if (gwarp >= NN) return;
    int n = gwarp;
    int beg = g_rowptr[n], end = g_rowptr[n + 1];

    float4 dA = *(const float4*)(g_aldP + n * 8);
    float2 dB = *(const float2*)(g_aldP + n * 8 + 4);
    float ald[6] = {dA.x, dA.y, dA.z, dA.w, dB.x, dB.y};

    // pass 1: online (max,sum) for 6 (conv,head) pairs
    float m[6], s[6];
#pragma unroll
    for (int k = 0; k < 6; k++) { m[k] = INF_NEG; s[k] = 0.f; }
    for (int i = beg + lane; i < end; i += 32) {
        int sv = g_srt[i];
        float4 sA = *(const float4*)(g_alsP + sv * 8);
        float4 sB = *(const float4*)(g_alsP + sv * 8 + 4);
        float als[6] = {sA.x, sA.y, sA.z, sA.w, sB.x, sB.y};
#pragma unroll
        for (int k = 0; k < 6; k++) {
            float e = lrelu(als[k] + ald[k]);
            float nm = fmaxf(m[k], e);
            s[k] = s[k] * __expf(m[k] - nm) + __expf(e - nm);
            m[k] = nm;
        }
    }
    for (int o = 16; o; o >>= 1) {
#pragma unroll
        for (int k = 0; k < 6; k++) {
            float om = __shfl_xor_sync(~0u, m[k], o);
            float os = __shfl_xor_sync(~0u, s[k], o);
            float nm = fmaxf(m[k], om);
            s[k] = s[k] * __expf(m[k] - nm) + os * __expf(om - nm);
            m[k] = nm;
        }
    }
    float inv[6];
#pragma unroll
    for (int k = 0; k < 6; k++) inv[k] = 1.f / (s[k] + 1e-16f);

    // pass 2: gather-accumulate (lanes>=16 are duplicates of lanes<16)
    int sub = lane & 15;
    int hh = (lane >> 3) & 1;
    float acc0 = 0.f, acc1 = 0.f, acc2 = 0.f;
    for (int base = beg; base < end; base += 32) {
        int idx = base + lane;
        int sl = 0;
        float p[6] = {0, 0, 0, 0, 0, 0};
        if (idx < end) {
            sl = g_srt[idx];
            float4 sA = *(const float4*)(g_alsP + sl * 8);
            float4 sB = *(const float4*)(g_alsP + sl * 8 + 4);
            float als[6] = {sA.x, sA.y, sA.z, sA.w, sB.x, sB.y};
#pragma unroll
            for (int k = 0; k < 6; k++)
                p[k] = __expf(lrelu(als[k] + ald[k]) - m[k]) * inv[k];
        }
        int cnt = min(32, end - base);
        for (int j = 0; j < cnt; j++) {
            int sb = __shfl_sync(~0u, sl, j);
            float q0 = __shfl_sync(~0u, p[0], j);
            float q1 = __shfl_sync(~0u, p[1], j);
            float q2 = __shfl_sync(~0u, p[2], j);
            float q3 = __shfl_sync(~0u, p[3], j);
            float q4 = __shfl_sync(~0u, p[4], j);
            float q5 = __shfl_sync(~0u, p[5], j);
            const float* gr = g_gall + (size_t)sb * 48;
            acc0 += (hh ? q1 : q0) * gr[sub];
            acc1 += (hh ? q3 : q2) * gr[16 + sub];
            acc2 += (hh ? q5 : q4) * gr[32 + sub];
        }
    }

    // head mean + bias + log_softmax (valid in lanes 0..7)
    float v0 = 0.5f * (acc0 + __shfl_xor_sync(~0u, acc0, 8)) + b_obj[lane & 7];
    float v1 = 0.5f * (acc1 + __shfl_xor_sync(~0u, acc1, 8)) + b_ctx[lane & 7];
    float v2 = 0.5f * (acc2 + __shfl_xor_sync(~0u, acc2, 8)) + b_co[lane & 7];
    float mv0 = v0, mv1 = v1, mv2 = v2;
    for (int o = 4; o; o >>= 1) {
        mv0 = fmaxf(mv0, __shfl_xor_sync(~0u, mv0, o, 8));
        mv1 = fmaxf(mv1, __shfl_xor_sync(~0u, mv1, o, 8));
        mv2 = fmaxf(mv2, __shfl_xor_sync(~0u, mv2, o, 8));
    }
    float se0 = __expf(v0 - mv0), se1 = __expf(v1 - mv1), se2 = __expf(v2 - mv2);
    for (int o = 4; o; o >>= 1) {
        se0 += __shfl_xor_sync(~0u, se0, o, 8);
        se1 += __shfl_xor_sync(~0u, se1, o, 8);
        se2 += __shfl_xor_sync(~0u, se2, o, 8);
    }
    if (lane < 8) {
        out[O0 + (size_t)n * 8 + lane] = v0 - mv0 - logf(se0);
        out[O1 + (size_t)n * 8 + lane] = v1 - mv1 - logf(se1);
        out[O2 + (size_t)n * 8 + lane] = v2 - mv2 - logf(se2);
    }
}

// ------------------- launch -------------------
extern "C" void kernel_launch(void* const* d_in, const int* in_sizes, int n_in,
                              void* d_out, int out_size) {
    const float* x      = (const float*)d_in[0];
    const int*   ei     = (const int*)d_in[1];     // int32 (JAX x64 disabled)
    const float* W_feat = (const float*)d_in[2];
    const float* a_s_f  = (const float*)d_in[3];
    const float* a_d_f  = (const float*)d_in[4];
    const float* b_feat = (const float*)d_in[5];
    const float* W_mlp  = (const float*)d_in[6];
    const float* b_mlp  = (const float*)d_in[7];
    const float* W_obj  = (const float*)d_in[8];
    const float* a_s_o  = (const float*)d_in[9];
    const float* a_d_o  = (const float*)d_in[10];
    const float* b_obj  = (const float*)d_in[11];
    const float* W_ctx  = (const float*)d_in[12];
    const float* a_s_c  = (const float*)d_in[13];
    const float* a_d_c  = (const float*)d_in[14];
    const float* b_ctx  = (const float*)d_in[15];
    const float* W_co   = (const float*)d_in[16];
    const float* a_s_x  = (const float*)d_in[17];
    const float* a_d_x  = (const float*)d_in[18];
    const float* b_co   = (const float*)d_in[19];
    float* out = (float*)d_out;

    k_zero_deg<<<(NN + 255) / 256, 256>>>();
    k_hist<<<(ET + 255) / 256, 256>>>(ei);
    k_scan<<<1, 1024>>>();
    k_scatter<<<(ET + 255) / 256, 256>>>(ei);

    k_gemm1<<<(NN + 63) / 64, 256>>>(x, W_feat, a_s_f, a_d_f);
    k_conv1<<<(NN + 3) / 4, 128>>>(b_feat, W_mlp, b_mlp, out);

    k_gemm2<<<NN / 16, 256>>>(W_obj, W_ctx, W_co,
                              a_s_o, a_d_o, a_s_c, a_d_c, a_s_x, a_d_x);

    k_conv2m<<<(NN + 3) / 4, 128>>>(b_obj, b_ctx, b_co, out);
}

// round 8
// speedup vs baseline: 1.3178x; 1.1267x over previous
#include <cuda_runtime.h>
#include <cstdint>

#define NN 50000
#define EE 800000
#define ET (EE + NN)
#define INF_NEG (-1e30f)

// output layout: xo_logis [N,8] | xc_logis [N,8] | xco_logis [N,8] | elu(xo) [N,256] | elu(xc) [N,256]
#define O0 0
#define O1 (NN*8)
#define O2 (2*NN*8)
#define O3 (3*NN*8)
#define O4 (3*NN*8 + NN*256)

typedef unsigned long long ull;

__device__ __forceinline__ ull pk2(float lo, float hi) {
    ull r; asm("mov.b64 %0, {%1, %2};" : "=l"(r) : "f"(lo), "f"(hi)); return r;
}
__device__ __forceinline__ void upk2(ull v, float& lo, float& hi) {
    asm("mov.b64 {%0, %1}, %2;" : "=f"(lo), "=f"(hi) : "l"(v));
}
#define FMA2(d, a, b) asm("fma.rn.f32x2 %0, %1, %2, %0;" : "+l"(d) : "l"(a), "l"(b))

// ------------------- static scratch -------------------
__device__ int   g_deg[NN];
__device__ int   g_rowptr[NN + 1];
__device__ int   g_wptr[NN];
__device__ int   g_srt[ET];

__device__ __align__(16) float  g_hfeat[(size_t)NN * 256];
__device__ __align__(16) float  g_h1[(size_t)NN * 256];
__device__ __align__(16) float2 g_att[NN];

__device__ __align__(16) float g_als[NN * 4], g_ald[NN * 4];
__device__ __align__(16) float g_gall[(size_t)NN * 48];
__device__ __align__(16) float g_alsP[NN * 8], g_aldP[NN * 8];

__device__ __forceinline__ float lrelu(float v) { return v > 0.f ? v : 0.2f * v; }
__device__ __forceinline__ float eluf(float v)  { return v > 0.f ? v : expm1f(v); }

// ------------------- CSR build -------------------
__global__ void k_zero_deg() {
    int i = blockIdx.x * blockDim.x + threadIdx.x;
    if (i < NN) g_deg[i] = 0;
}

__global__ void k_hist(const int* __restrict__ ei) {
    int i = blockIdx.x * blockDim.x + threadIdx.x;
    if (i >= ET) return;
    int d = (i < EE) ? ei[EE + i] : (i - EE);
    atomicAdd(&g_deg[d], 1);
}

__global__ void k_scan() {
    __shared__ int sums[1024];
    int tid = threadIdx.x;
    const int chunk = (NN + 1023) / 1024;
    int start = tid * chunk;
    int s = 0;
    for (int i = 0; i < chunk; i++) {
        int idx = start + i;
        if (idx < NN) s += g_deg[idx];
    }
    sums[tid] = s;
    __syncthreads();
    for (int off = 1; off < 1024; off <<= 1) {
        int v = 0;
        if (tid >= off) v = sums[tid - off];
        __syncthreads();
        if (tid >= off) sums[tid] += v;
        __syncthreads();
    }
    int prefix = (tid == 0) ? 0 : sums[tid - 1];
    for (int i = 0; i < chunk; i++) {
        int idx = start + i;
        if (idx < NN) {
            g_rowptr[idx] = prefix;
            g_wptr[idx] = prefix;
            prefix += g_deg[idx];
        }
    }
    if (tid == 0) g_rowptr[NN] = sums[1023];
}

__global__ void k_scatter(const int* __restrict__ ei) {
    int i = blockIdx.x * blockDim.x + threadIdx.x;
    if (i >= ET) return;
    int s, d;
    if (i < EE) { s = ei[i]; d = ei[EE + i]; }
    else        { s = d = i - EE; }
    int pos = atomicAdd(&g_wptr[d], 1);
    g_srt[pos] = s;
}

// ------------------- GEMM1: 64x256 tile, thread = 8 rows x (4+4 split cols), f32x2 -------------------
__global__ __launch_bounds__(256) void k_gemm1(
    const float* __restrict__ x, const float* __restrict__ Wf,
    const float* __restrict__ a_s, const float* __restrict__ a_d) {
    __shared__ float xs[64][132];
    __shared__ float Bs[8][256];
    int tid = threadIdx.x;
    int n0 = blockIdx.x * 64;
    int ty = tid >> 5, tx = tid & 31;

#pragma unroll
    for (int i = 0; i < 8; i++) {
        int idx4 = tid + i * 256;
        int row = idx4 >> 5, kq = idx4 & 31;
        float4 v = make_float4(0, 0, 0, 0);
        if (n0 + row < NN) v = *(const float4*)(x + (size_t)(n0 + row) * 128 + kq * 4);
        *(float4*)&xs[row][kq * 4] = v;
    }

    float4 asA = *(const float4*)(a_s + tx * 4);
    float4 asB = *(const float4*)(a_s + 128 + tx * 4);
    float4 adA = *(const float4*)(a_d + tx * 4);
    float4 adB = *(const float4*)(a_d + 128 + tx * 4);

    ull accp[8][4];
#pragma unroll
    for (int i = 0; i < 8; i++)
#pragma unroll
        for (int j = 0; j < 4; j++) accp[i][j] = 0ull;

    for (int kt = 0; kt < 16; kt++) {
        __syncthreads();
#pragma unroll
        for (int i = 0; i < 2; i++) {
            int idx4 = tid + i * 256;
            int kk = idx4 >> 6, col4 = (idx4 & 63) * 4;
            *(float4*)&Bs[kk][col4] = *(const float4*)(Wf + (size_t)(kt * 8 + kk) * 256 + col4);
        }
        __syncthreads();
#pragma unroll
        for (int kk = 0; kk < 8; kk++) {
            float4 bA = *(float4*)&Bs[kk][tx * 4];
            float4 bB = *(float4*)&Bs[kk][128 + tx * 4];
            ull b0 = pk2(bA.x, bA.y), b1 = pk2(bA.z, bA.w);
            ull b2 = pk2(bB.x, bB.y), b3 = pk2(bB.z, bB.w);
#pragma unroll
            for (int i = 0; i < 8; i++) {
                float a = xs[ty * 8 + i][kt * 8 + kk];
                ull aa = pk2(a, a);
                FMA2(accp[i][0], aa, b0);
                FMA2(accp[i][1], aa, b1);
                FMA2(accp[i][2], aa, b2);
                FMA2(accp[i][3], aa, b3);
            }
        }
    }

    // epilogue: store hfeat + fused attention-logit dots
#pragma unroll
    for (int i = 0; i < 8; i++) {
        int row = n0 + ty * 8 + i;
        bool ok = row < NN;
        float4 vA, vB;
        upk2(accp[i][0], vA.x, vA.y); upk2(accp[i][1], vA.z, vA.w);
        upk2(accp[i][2], vB.x, vB.y); upk2(accp[i][3], vB.z, vB.w);
        if (ok) {
            *(float4*)(g_hfeat + (size_t)row * 256 + tx * 4)       = vA;
            *(float4*)(g_hfeat + (size_t)row * 256 + 128 + tx * 4) = vB;
        }
        float psA = vA.x * asA.x + vA.y * asA.y + vA.z * asA.z + vA.w * asA.w;
        float psB = vB.x * asB.x + vB.y * asB.y + vB.z * asB.z + vB.w * asB.w;
        float pdA = vA.x * adA.x + vA.y * adA.y + vA.z * adA.z + vA.w * adA.w;
        float pdB = vB.x * adB.x + vB.y * adB.y + vB.z * adB.z + vB.w * adB.w;
        for (int o = 1; o < 16; o <<= 1) {
            psA += __shfl_xor_sync(~0u, psA, o);
            psB += __shfl_xor_sync(~0u, psB, o);
            pdA += __shfl_xor_sync(~0u, pdA, o);
            pdB += __shfl_xor_sync(~0u, pdB, o);
        }
        if ((tx & 15) == 0 && ok) {
            int hA = tx >> 4;   // lanes 0/16 -> heads (0,2)/(1,3)
            g_als[row * 4 + hA]     = psA;
            g_als[row * 4 + 2 + hA] = psB;
            g_ald[row * 4 + hA]     = pdA;
            g_ald[row * 4 + 2 + hA] = pdB;
        }
    }
}

// ------------------- big conv: warp per dst node, SINGLE pass, f32x2 gather -------------------
__global__ void k_conv1(const float* __restrict__ b_feat, const float* __restrict__ W_mlp,
                        const float* __restrict__ b_mlp, float* __restrict__ out) {
    int gwarp = (blockIdx.x * blockDim.x + threadIdx.x) >> 5;
    int lane = threadIdx.x & 31;
    if (gwarp >= NN) return;
    int n = gwarp;
    int beg = g_rowptr[n], end = g_rowptr[n + 1];

    const float4* als4 = (const float4*)g_als;
    float4 ad = ((const float4*)g_ald)[n];

    float s0 = 0.f, s1 = 0.f, s2 = 0.f, s3 = 0.f;
    ull accp[4] = {0ull, 0ull, 0ull, 0ull};

    for (int base = beg; base < end; base += 32) {
        int idx = base + lane;
        int sl = 0;
        float p0 = 0.f, p1 = 0.f, p2 = 0.f, p3 = 0.f;
        if (idx < end) {
            sl = g_srt[idx];
            float4 as = als4[sl];
            p0 = __expf(lrelu(as.x + ad.x));
            p1 = __expf(lrelu(as.y + ad.y));
            p2 = __expf(lrelu(as.z + ad.z));
            p3 = __expf(lrelu(as.w + ad.w));
            s0 += p0; s1 += p1; s2 += p2; s3 += p3;
        }
        int cnt = min(32, end - base);
        for (int j = 0; j < cnt; j++) {
            int sb = __shfl_sync(~0u, sl, j);
            float a0 = __shfl_sync(~0u, p0, j);
            float a1 = __shfl_sync(~0u, p1, j);
            float a2 = __shfl_sync(~0u, p2, j);
            float a3 = __shfl_sync(~0u, p3, j);
            const ull* hr = (const ull*)(g_hfeat + (size_t)sb * 256);
            ull h0 = hr[lane], h1 = hr[lane + 32], h2 = hr[lane + 64], h3 = hr[lane + 96];
            FMA2(accp[0], pk2(a0, a0), h0);
            FMA2(accp[1], pk2(a1, a1), h1);
            FMA2(accp[2], pk2(a2, a2), h2);
            FMA2(accp[3], pk2(a3, a3), h3);
        }
    }

    for (int o = 16; o; o >>= 1) {
        s0 += __shfl_xor_sync(~0u, s0, o);
        s1 += __shfl_xor_sync(~0u, s1, o);
        s2 += __shfl_xor_sync(~0u, s2, o);
        s3 += __shfl_xor_sync(~0u, s3, o);
    }
    float invk[4];
    invk[0] = 1.f / (s0 + 1e-16f); invk[1] = 1.f / (s1 + 1e-16f);
    invk[2] = 1.f / (s2 + 1e-16f); invk[3] = 1.f / (s3 + 1e-16f);

    // epilogue: normalize, h1 = elu(. + b); MLP softmax; elu(xo)/elu(xc)
    float he[8];
    float l0 = 0.f, l1 = 0.f;
#pragma unroll
    for (int k = 0; k < 4; k++) {
        float lo, hi;
        upk2(accp[k], lo, hi);
        int pi = lane + 32 * k;
        int c0 = 2 * pi;
        float2 bf = *(const float2*)(b_feat + c0);
        float ha = eluf(lo * invk[k] + bf.x);
        float hb = eluf(hi * invk[k] + bf.y);
        he[2 * k] = ha; he[2 * k + 1] = hb;
        *(float2*)(g_h1 + (size_t)n * 256 + c0) = make_float2(ha, hb);
        float4 wm = *(const float4*)(W_mlp + 4 * pi);
        l0 += ha * wm.x + hb * wm.z;
        l1 += ha * wm.y + hb * wm.w;
    }
    for (int o = 16; o; o >>= 1) {
        l0 += __shfl_xor_sync(~0u, l0, o);
        l1 += __shfl_xor_sync(~0u, l1, o);
    }
    l0 += b_mlp[0];
    l1 += b_mlp[1];
    float mm = fmaxf(l0, l1);
    float e0 = __expf(l0 - mm), e1 = __expf(l1 - mm);
    float inv2 = 1.f / (e0 + e1);
    float att0 = e0 * inv2, att1 = e1 * inv2;
    if (lane == 0) g_att[n] = make_float2(att0, att1);
#pragma unroll
    for (int k = 0; k < 4; k++) {
        int c0 = 2 * (lane + 32 * k);
        *(float2*)(out + O3 + (size_t)n * 256 + c0) =
            make_float2(eluf(att0 * he[2 * k]), eluf(att0 * he[2 * k + 1]));
        *(float2*)(out + O4 + (size_t)n * 256 + c0) =
            make_float2(eluf(att1 * he[2 * k]), eluf(att1 * he[2 * k + 1]));
    }
}

// ------------------- GEMM2: Y = h1 @ [Wobj|Wctx|Wco] (att-scaled), + logit dots, f32x2 -------------------
__global__ __launch_bounds__(256) void k_gemm2(
    const float* __restrict__ Wo, const float* __restrict__ Wc, const float* __restrict__ Wx,
    const float* __restrict__ aso, const float* __restrict__ ado,
    const float* __restrict__ asc, const float* __restrict__ adc,
    const float* __restrict__ asx, const float* __restrict__ adx) {
    __shared__ float sh[16][266];   // stride 1064B: 8-aligned, NOT 16 — float2/ull access only!
    __shared__ float ws[16][266];
    __shared__ float ysm[16][52];
    int tid = threadIdx.x;
    int n0 = blockIdx.x * 16;

    // fill sh with float2 (stride is 8-byte aligned, not 16)
#pragma unroll
    for (int i = 0; i < 8; i++) {
        int idx2 = tid + i * 256;          // 2048 float2 = 16 rows x 128
        int row = idx2 >> 7, kq = idx2 & 127;
        *(float2*)&sh[row][kq * 2] = *(const float2*)(g_h1 + (size_t)(n0 + row) * 256 + kq * 2);
    }

    int node = tid >> 4, c = tid & 15;
    float2 att = g_att[n0 + node];

    for (int v = 0; v < 3; v++) {
        const float* W = (v == 0) ? Wo : (v == 1) ? Wc : Wx;
        float scale = (v == 0) ? att.x : (v == 1) ? att.y : 1.f;
        __syncthreads();
#pragma unroll
        for (int i = 0; i < 16; i++) {
            int idx = tid + i * 256;
            ws[idx & 15][idx >> 4] = W[idx];
        }
        __syncthreads();
        const ull* h2 = (const ull*)&sh[node][0];
        const ull* w2 = (const ull*)&ws[c][0];
        ull ap = 0ull;
#pragma unroll 16
        for (int k = 0; k < 128; k++) FMA2(ap, h2[k], w2[k]);
        float lo, hi;
        upk2(ap, lo, hi);
        float y = (lo + hi) * scale;
        g_gall[(size_t)(n0 + node) * 48 + v * 16 + c] = y;
        ysm[node][v * 16 + c] = y;
    }
    __syncthreads();
    if (tid < 192) {
        int nd = tid / 12, r = tid % 12;
        int v = r >> 2, h = (r >> 1) & 1, sd = r & 1;
        const float* a = sd ? ((v == 0) ? ado : (v == 1) ? adc : adx)
                            : ((v == 0) ? aso : (v == 1) ? asc : asx);
        float s = 0.f;
#pragma unroll
        for (int o = 0; o < 8; o++) s += ysm[nd][v * 16 + h * 8 + o] * a[h * 8 + o];
        float* dstp = sd ? g_aldP : g_alsP;
        dstp[(n0 + nd) * 8 + v * 2 + h] = s;
    }
}

// ------------------- merged small convs: warp per dst node, SINGLE pass -------------------
__global__ void k_conv2m(const float* __restrict__ b_obj, const float* __restrict__ b_ctx,
                         const float* __restrict__ b_co, float* __restrict__ out) {
    int gwarp = (blockIdx.x * blockDim.x + threadIdx.x) >> 5;
    int lane = threadIdx.x & 31;
    if (gwarp >= NN) return;
    int n = gwarp;
    int beg = g_rowptr[n], end = g_rowptr[n + 1];

    float4 dA = *(const float4*)(g_aldP + n * 8);
    float2 dB = *(const float2*)(g_aldP + n * 8 + 4);
    float ald[6] = {dA.x, dA.y, dA.z, dA.w, dB.x, dB.y};

    int sub = lane & 15;
    int hh = (lane >> 3) & 1;
    float s[6] = {0, 0, 0, 0, 0, 0};
    float acc0 = 0.f, acc1 = 0.f, acc2 = 0.f;

    for (int base = beg; base < end; base += 32) {
        int idx = base + lane;
        int sl = 0;
        float p[6] = {0, 0, 0, 0, 0, 0};
        if (idx < end) {
            sl = g_srt[idx];
            float4 sA = *(const float4*)(g_alsP + sl * 8);
            float2 sB = *(const float2*)(g_alsP + sl * 8 + 4);
            float als[6] = {sA.x, sA.y, sA.z, sA.w, sB.x, sB.y};
#pragma unroll
            for (int k = 0; k < 6; k++) {
                p[k] = __expf(lrelu(als[k] + ald[k]));
                s[k] += p[k];
            }
        }
        int cnt = min(32, end - base);
        for (int j = 0; j < cnt; j++) {
            int sb = __shfl_sync(~0u, sl, j);
            float q0 = __shfl_sync(~0u, p[0], j);
            float q1 = __shfl_sync(~0u, p[1], j);
            float q2 = __shfl_sync(~0u, p[2], j);
            float q3 = __shfl_sync(~0u, p[3], j);
            float q4 = __shfl_sync(~0u, p[4], j);
            float q5 = __shfl_sync(~0u, p[5], j);
            const float* gr = g_gall + (size_t)sb * 48;
            acc0 += (hh ? q1 : q0) * gr[sub];
            acc1 += (hh ? q3 : q2) * gr[16 + sub];
            acc2 += (hh ? q5 : q4) * gr[32 + sub];
        }
    }

    for (int o = 16; o; o >>= 1) {
#pragma unroll
        for (int k = 0; k < 6; k++) s[k] += __shfl_xor_sync(~0u, s[k], o);
    }
    acc0 *= 1.f / (s[hh] + 1e-16f);
    acc1 *= 1.f / (s[2 + hh] + 1e-16f);
    acc2 *= 1.f / (s[4 + hh] + 1e-16f);

    // head mean + bias + log_softmax (valid in lanes 0..7)
    float v0 = 0.5f * (acc0 + __shfl_xor_sync(~0u, acc0, 8)) + b_obj[lane & 7];
    float v1 = 0.5f * (acc1 + __shfl_xor_sync(~0u, acc1, 8)) + b_ctx[lane & 7];
    float v2 = 0.5f * (acc2 + __shfl_xor_sync(~0u, acc2, 8)) + b_co[lane & 7];
    float mv0 = v0, mv1 = v1, mv2 = v2;
    for (int o = 4; o; o >>= 1) {
        mv0 = fmaxf(mv0, __shfl_xor_sync(~0u, mv0, o, 8));
        mv1 = fmaxf(mv1, __shfl_xor_sync(~0u, mv1, o, 8));
        mv2 = fmaxf(mv2, __shfl_xor_sync(~0u, mv2, o, 8));
    }
    float se0 = __expf(v0 - mv0), se1 = __expf(v1 - mv1), se2 = __expf(v2 - mv2);
    for (int o = 4; o; o >>= 1) {
        se0 += __shfl_xor_sync(~0u, se0, o, 8);
        se1 += __shfl_xor_sync(~0u, se1, o, 8);
        se2 += __shfl_xor_sync(~0u, se2, o, 8);
    }
    if (lane < 8) {
        out[O0 + (size_t)n * 8 + lane] = v0 - mv0 - logf(se0);
        out[O1 + (size_t)n * 8 + lane] = v1 - mv1 - logf(se1);
        out[O2 + (size_t)n * 8 + lane] = v2 - mv2 - logf(se2);
    }
}

// ------------------- launch -------------------
extern "C" void kernel_launch(void* const* d_in, const int* in_sizes, int n_in,
                              void* d_out, int out_size) {
    const float* x      = (const float*)d_in[0];
    const int*   ei     = (const int*)d_in[1];
    const float* W_feat = (const float*)d_in[2];
    const float* a_s_f  = (const float*)d_in[3];
    const float* a_d_f  = (const float*)d_in[4];
    const float* b_feat = (const float*)d_in[5];
    const float* W_mlp  = (const float*)d_in[6];
    const float* b_mlp  = (const float*)d_in[7];
    const float* W_obj  = (const float*)d_in[8];
    const float* a_s_o  = (const float*)d_in[9];
    const float* a_d_o  = (const float*)d_in[10];
    const float* b_obj  = (const float*)d_in[11];
    const float* W_ctx  = (const float*)d_in[12];
    const float* a_s_c  = (const float*)d_in[13];
    const float* a_d_c  = (const float*)d_in[14];
    const float* b_ctx  = (const float*)d_in[15];
    const float* W_co   = (const float*)d_in[16];
    const float* a_s_x  = (const float*)d_in[17];
    const float* a_d_x  = (const float*)d_in[18];
    const float* b_co   = (const float*)d_in[19];
    float* out = (float*)d_out;

    k_zero_deg<<<(NN + 255) / 256, 256>>>();
    k_hist<<<(ET + 255) / 256, 256>>>(ei);
    k_scan<<<1, 1024>>>();
    k_scatter<<<(ET + 255) / 256, 256>>>(ei);

    k_gemm1<<<(NN + 63) / 64, 256>>>(x, W_feat, a_s_f, a_d_f);
    k_conv1<<<(NN + 3) / 4, 128>>>(b_feat, W_mlp, b_mlp, out);

    k_gemm2<<<NN / 16, 256>>>(W_obj, W_ctx, W_co,
                              a_s_o, a_d_o, a_s_c, a_d_c, a_s_x, a_d_x);

    k_conv2m<<<(NN + 3) / 4, 128>>>(b_obj, b_ctx, b_co, out);
}